// round 3
// baseline (speedup 1.0000x reference)
#include <cuda_runtime.h>
#include <cstdint>

// Problem constants: features (B, D, L) f32, tois (B, N, 2) i32, MAX_SPAN=64
#define BB 16
#define DD 256
#define LL 4096
#define NQ 4096

// Scratch: chunk-local (64-wide) inclusive cumsum, transposed layout [B][L][D].
// 64 MB -> fits L2 (126 MB); k_pool gathers should be L2 hits. Output stores
// use streaming (.cs) so they don't evict this from L2.
__device__ float g_ic[(size_t)BB * LL * DD];

// ---------------------------------------------------------------------------
// Kernel 1: tile transpose + chunk-local (64-wide) inclusive scan.
// One block handles (b, 32 d-rows, 64 l-columns). Scan restarts at every
// 64-aligned chunk; spans never exceed 64, so a span straddles at most one
// chunk boundary.
// ---------------------------------------------------------------------------
__global__ void __launch_bounds__(256) k_scan(const float* __restrict__ feat) {
    __shared__ float icT[64][33];

    const int l0 = blockIdx.x << 6;   // l chunk base (multiple of 64)
    const int d0 = blockIdx.y << 5;   // d base (multiple of 32)
    const int b  = blockIdx.z;
    const int tid  = threadIdx.x;
    const int w    = tid >> 5;
    const int lane = tid & 31;

    // Each warp scans 4 d-rows; each lane loads a contiguous float2 (256B/row).
    // Streaming loads: features are read exactly once.
    #pragma unroll
    for (int r = 0; r < 4; r++) {
        const int dd = (w << 2) + r;
        const float2* row = reinterpret_cast<const float2*>(
            feat + ((size_t)b * DD + d0 + dd) * LL + l0);
        float2 v = __ldcs(row + lane);
        float s = v.x + v.y;
        // warp-inclusive scan of pair sums
        #pragma unroll
        for (int o = 1; o < 32; o <<= 1) {
            float t = __shfl_up_sync(0xffffffffu, s, o);
            if (lane >= o) s += t;
        }
        icT[2 * lane    ][dd] = s - v.y;  // inclusive prefix at 2*lane
        icT[2 * lane + 1][dd] = s;        // inclusive prefix at 2*lane+1
    }
    __syncthreads();

    // Coalesced transposed writes: 32 consecutive d per 128B segment.
    const size_t gb = ((size_t)b * LL + l0) * DD + d0;
    #pragma unroll
    for (int k = 0; k < 8; k++) {
        const int e  = tid + (k << 8);
        const int ll = e >> 5;
        const int dd = e & 31;
        g_ic[gb + (size_t)ll * DD + dd] = icT[ll][dd];
    }
}

// ---------------------------------------------------------------------------
// Kernel 2: 4 queries per 256-thread block; 64 threads per query, each thread
// owns a float4 of d. Five UNCONDITIONAL independent loads per thread
// (MLP=5), blended with 0/1 weights; streaming stores keep L2 for scratch.
// ---------------------------------------------------------------------------
__global__ void __launch_bounds__(256) k_pool(const int* __restrict__ tois,
                                              float* __restrict__ out,
                                              int write_counts) {
    const int qq  = threadIdx.x >> 6;                 // query slot 0..3
    const int t64 = threadIdx.x & 63;                 // float4 lane within d
    const int q   = (blockIdx.x << 2) + qq;           // global query id
    const int b   = q >> 12;                          // N = 4096

    const int2 t  = __ldg(reinterpret_cast<const int2*>(tois) + q);
    const int start = t.x;
    const int e     = t.y - 1;

    const int sm1 = (start > 0) ? start - 1 : 0;      // clamped; weight 0 if unused
    const int em1 = (e > 0) ? e - 1 : 0;
    const int ce  = (start & ~63) | 63;               // end of start's chunk

    const float fB = (start & 63)            ? 1.0f : 0.0f;
    const float fD = (e & 63)                ? 1.0f : 0.0f;
    const float fE = ((e >> 6) != (start >> 6)) ? 1.0f : 0.0f;

    const float4* __restrict__ ic = reinterpret_cast<const float4*>(g_ic);
    const size_t rowBase = (size_t)b * LL;
    #define LDROW(l) __ldg(ic + (rowBase + (size_t)(l)) * 64 + t64)

    // 5 independent loads, all issued before any use.
    const float4 A = LDROW(start);   // ic[start]
    const float4 C = LDROW(e);       // ic[e]
    const float4 Bv = LDROW(sm1);    // ic[start-1]
    const float4 Dv = LDROW(em1);    // ic[e-1]
    const float4 Ev = LDROW(ce);     // ic[chunk_end(start)]
    #undef LDROW

    const float inv = 1.0f / (float)(t.y - start);

    float4 head, tail, avg;
    head.x = fmaf(-fB, Bv.x, A.x);  head.y = fmaf(-fB, Bv.y, A.y);
    head.z = fmaf(-fB, Bv.z, A.z);  head.w = fmaf(-fB, Bv.w, A.w);

    tail.x = fmaf(-fD, Dv.x, C.x);  tail.y = fmaf(-fD, Dv.y, C.y);
    tail.z = fmaf(-fD, Dv.z, C.z);  tail.w = fmaf(-fD, Dv.w, C.w);

    avg.x = (head.x == head.x) ? 0.f : 0.f; // (placeholder removed by folding)
    float nx = fmaf(fE, Ev.x, fmaf(-fB, Bv.x, C.x));
    float ny = fmaf(fE, Ev.y, fmaf(-fB, Bv.y, C.y));
    float nz = fmaf(fE, Ev.z, fmaf(-fB, Bv.z, C.z));
    float nw = fmaf(fE, Ev.w, fmaf(-fB, Bv.w, C.w));
    avg.x = nx * inv; avg.y = ny * inv; avg.z = nz * inv; avg.w = nw * inv;

    // Streaming stores: output is write-once, keep it out of L2's way.
    float4* o = reinterpret_cast<float4*>(out + (size_t)q * (3 * DD));
    __stcs(o + t64,        head);   // [0,256)
    __stcs(o + 64 + t64,   avg);    // [256,512)
    __stcs(o + 128 + t64,  tail);   // [512,768)

    // counts output: cumsum of per-batch query counts = [N, 2N, ..., B*N]
    if (write_counts && q == 0 && t64 < BB && qq == 0) {
        out[(size_t)BB * NQ * 3 * DD + t64] = (float)((t64 + 1) * NQ);
    }
}

extern "C" void kernel_launch(void* const* d_in, const int* in_sizes, int n_in,
                              void* d_out, int out_size) {
    const float* feat = (const float*)d_in[0];
    const int*   tois = (const int*)d_in[1];
    float*       out  = (float*)d_out;

    const long long total = (long long)BB * NQ * 3 * DD;  // 50,331,648
    const int write_counts = ((long long)out_size >= total + BB) ? 1 : 0;

    dim3 g1(LL / 64, DD / 32, BB);    // 64 x 8 x 16 = 8192 blocks
    k_scan<<<g1, 256>>>(feat);
    k_pool<<<(BB * NQ) / 4, 256>>>(tois, out, write_counts);
}

// round 4
// speedup vs baseline: 1.0585x; 1.0585x over previous
#include <cuda_runtime.h>
#include <cstdint>

// Problem constants: features (B, D, L) f32, tois (B, N, 2) i32, MAX_SPAN=64
#define BB 16
#define DD 256
#define LL 4096
#define NQ 4096

// Scratch: chunk-local (64-wide) inclusive cumsum, transposed layout [B][L][D].
// 64 MB -> fits L2 (126 MB), so k_pool gathers are mostly L2 hits.
__device__ float g_ic[(size_t)BB * LL * DD];

// ---------------------------------------------------------------------------
// Kernel 1: tile transpose + chunk-local (64-wide) inclusive scan.
// One block handles (b, 64 d-rows, 64 l-columns). Scan restarts at every
// 64-aligned chunk; spans never exceed 64, so any span straddles at most one
// chunk boundary. Store phase uses float4 (STG.128) transposed writes.
// ---------------------------------------------------------------------------
__global__ void __launch_bounds__(256) k_scan(const float* __restrict__ feat) {
    __shared__ float icT[64][65];     // [l][d], padded

    const int l0 = blockIdx.x << 6;   // l chunk base (multiple of 64)
    const int d0 = blockIdx.y << 6;   // d base (multiple of 64)
    const int b  = blockIdx.z;
    const int tid  = threadIdx.x;
    const int w    = tid >> 5;
    const int lane = tid & 31;

    // Each warp scans 8 d-rows; each lane loads a contiguous float2 (256B/row).
    // Streaming loads: features are read exactly once; keep L2 for g_ic.
    #pragma unroll
    for (int r = 0; r < 8; r++) {
        const int dd = (w << 3) + r;
        const float2* row = reinterpret_cast<const float2*>(
            feat + ((size_t)b * DD + d0 + dd) * LL + l0);
        float2 v = __ldcs(row + lane);
        float s = v.x + v.y;
        // warp-inclusive scan of pair sums
        #pragma unroll
        for (int o = 1; o < 32; o <<= 1) {
            float t = __shfl_up_sync(0xffffffffu, s, o);
            if (lane >= o) s += t;
        }
        icT[2 * lane    ][dd] = s - v.y;  // inclusive prefix at 2*lane
        icT[2 * lane + 1][dd] = s;        // inclusive prefix at 2*lane+1
    }
    __syncthreads();

    // Transposed writes as float4: 16 threads cover one 64-d row (256B),
    // fully coalesced STG.128.
    const size_t gq = (((size_t)b * LL + l0) * DD + d0) >> 2;  // float4 index
    float4* __restrict__ out4 = reinterpret_cast<float4*>(g_ic);
    #pragma unroll
    for (int k = 0; k < 4; k++) {
        const int e  = tid + (k << 8);      // 0..1023 float4 slots
        const int ll = e >> 4;              // l row
        const int qd = e & 15;              // float4 within the 64-d segment
        float4 v;
        v.x = icT[ll][4 * qd    ];
        v.y = icT[ll][4 * qd + 1];
        v.z = icT[ll][4 * qd + 2];
        v.w = icT[ll][4 * qd + 3];
        out4[gq + (size_t)ll * (DD / 4) + qd] = v;
    }
}

// ---------------------------------------------------------------------------
// Kernel 2 (R2 version — measured LTS-saturated at ~42us):
// 4 queries per 256-thread block; 64 threads per query, each thread owns a
// float4 of d. Conditional loads (fewer bytes on average beats higher MLP).
// ---------------------------------------------------------------------------
__global__ void __launch_bounds__(256) k_pool(const int* __restrict__ tois,
                                              float* __restrict__ out,
                                              int write_counts) {
    const int qq  = threadIdx.x >> 6;                 // query slot 0..3
    const int t64 = threadIdx.x & 63;                 // float4 lane within d
    const int q   = (blockIdx.x << 2) + qq;           // global query id
    const int b   = q >> 12;                          // N = 4096

    const int2 t  = reinterpret_cast<const int2*>(tois)[q];
    const int start = t.x;
    const int e     = t.y - 1;

    const float4* __restrict__ ic = reinterpret_cast<const float4*>(g_ic);
    const size_t rowBase = (size_t)b * LL;            // in rows
    #define LDROW(l) ic[(rowBase + (size_t)(l)) * 64 + t64]

    const float4 A = LDROW(start);                    // ic[start]
    const float4 C = LDROW(e);                        // ic[e]

    float4 head = A;
    float4 tail = C;
    float4 num  = C;

    if (start & 63) {                                 // uniform per query
        const float4 Bv = LDROW(start - 1);
        head.x = A.x - Bv.x; head.y = A.y - Bv.y;
        head.z = A.z - Bv.z; head.w = A.w - Bv.w;
        num.x -= Bv.x; num.y -= Bv.y; num.z -= Bv.z; num.w -= Bv.w;
    }
    if (e & 63) {
        const float4 Dv = LDROW(e - 1);
        tail.x = C.x - Dv.x; tail.y = C.y - Dv.y;
        tail.z = C.z - Dv.z; tail.w = C.w - Dv.w;
    }
    if ((e >> 6) != (start >> 6)) {                   // span straddles a chunk edge
        const float4 Ev = LDROW((start & ~63) + 63);  // full tail of start chunk
        num.x += Ev.x; num.y += Ev.y; num.z += Ev.z; num.w += Ev.w;
    }
    #undef LDROW

    const float inv = 1.0f / (float)(t.y - start);
    float4 avg;
    avg.x = num.x * inv; avg.y = num.y * inv;
    avg.z = num.z * inv; avg.w = num.w * inv;

    float4* o = reinterpret_cast<float4*>(out + (size_t)q * (3 * DD));
    o[t64]       = head;   // [0,256)
    o[64 + t64]  = avg;    // [256,512)
    o[128 + t64] = tail;   // [512,768)

    // counts output: cumsum of per-batch query counts = [N, 2N, ..., B*N]
    if (write_counts && q == 0 && t64 < BB && qq == 0) {
        out[(size_t)BB * NQ * 3 * DD + t64] = (float)((t64 + 1) * NQ);
    }
}

extern "C" void kernel_launch(void* const* d_in, const int* in_sizes, int n_in,
                              void* d_out, int out_size) {
    const float* feat = (const float*)d_in[0];
    const int*   tois = (const int*)d_in[1];
    float*       out  = (float*)d_out;

    const long long total = (long long)BB * NQ * 3 * DD;  // 50,331,648
    const int write_counts = ((long long)out_size >= total + BB) ? 1 : 0;

    dim3 g1(LL / 64, DD / 64, BB);    // 64 x 4 x 16 = 4096 blocks
    k_scan<<<g1, 256>>>(feat);
    k_pool<<<(BB * NQ) / 4, 256>>>(tois, out, write_counts);
}